// round 2
// baseline (speedup 1.0000x reference)
#include <cuda_runtime.h>
#include <cuda_fp16.h>

typedef unsigned long long ull;

#define BB   8
#define MM   4096
#define NN   16384
#define HH   128
#define WW   128
#define BN   (BB*NN)
#define TAUF 0.01f
#define EPSF 1e-8f
#define ITERS 100

// ---------------- device state (no allocations allowed) ----------------
__device__ __half g_Ah[(size_t)MM * NN];          // A in fp16, 128 MB
__device__ float  g_x[BN];
__device__ float  g_xbar[BN];
__device__ float  g_t[BN];
__device__ float  g_yb[2][2][BN];                 // ping-pong y, 2 components
__device__ float  g_rpart[2][MM][BB];             // phase-1 K-split partials
__device__ float  g_gpart[16 * BB * NN];          // phase-2 M-split partials (8 MB)

// ---------------- packed f32x2 helpers ----------------
__device__ __forceinline__ ull pack2(float x, float y) {
    ull r;
    asm("mov.b64 %0, {%1, %2};" : "=l"(r) : "f"(x), "f"(y));
    return r;
}
__device__ __forceinline__ float2 unpack2(ull v) {
    float x, y;
    asm("mov.b64 {%0, %1}, %2;" : "=f"(x), "=f"(y) : "l"(v));
    return make_float2(x, y);
}
__device__ __forceinline__ ull fma2(ull a, ull b, ull c) {
    ull d;
    asm("fma.rn.f32x2 %0, %1, %2, %3;" : "=l"(d) : "l"(a), "l"(b), "l"(c));
    return d;
}
__device__ __forceinline__ ull h2_to_f32x2(__half2 h) {
    float2 f = __half22float2(h);
    return pack2(f.x, f.y);
}

// ---------------- A fp32 -> fp16 conversion ----------------
__global__ void k_convert(const float* __restrict__ A) {
    size_t gid = (size_t)blockIdx.x * blockDim.x + threadIdx.x;   // each handles 8
    size_t base = gid * 8;
    float4 a = *reinterpret_cast<const float4*>(A + base);
    float4 b = *reinterpret_cast<const float4*>(A + base + 4);
    __half2 h0 = __floats2half2_rn(a.x, a.y);
    __half2 h1 = __floats2half2_rn(a.z, a.w);
    __half2 h2 = __floats2half2_rn(b.x, b.y);
    __half2 h3 = __floats2half2_rn(b.z, b.w);
    uint4 o;
    o.x = *reinterpret_cast<unsigned*>(&h0);
    o.y = *reinterpret_cast<unsigned*>(&h1);
    o.z = *reinterpret_cast<unsigned*>(&h2);
    o.w = *reinterpret_cast<unsigned*>(&h3);
    reinterpret_cast<uint4*>(g_Ah)[gid] = o;
}

// ---------------- zero init ----------------
__global__ void k_zero() {
    int idx = blockIdx.x * blockDim.x + threadIdx.x;
    if (idx < BN) {
        g_x[idx] = 0.f; g_xbar[idx] = 0.f;
        g_yb[0][0][idx] = 0.f; g_yb[0][1][idx] = 0.f;
    }
}

// ---------------- TV stencil: t = x - tau*div(y);  y' = normalize(y + tau*grad(xbar)) ----
__global__ void k_tv(int bi) {
    int idx = blockIdx.x * blockDim.x + threadIdx.x;
    if (idx >= BN) return;
    int p = idx & (NN - 1);
    int i = p >> 7;          // row in 128x128
    int j = p & 127;

    const float* yx = g_yb[bi][0];
    const float* yy = g_yb[bi][1];
    float*       oyx = g_yb[bi ^ 1][0];
    float*       oyy = g_yb[bi ^ 1][1];

    float yxv = yx[idx];
    float yyv = yy[idx];

    // divergence (matches jnp.pad front-padding exactly)
    float dx = (j > 0)  ? (yxv - yx[idx - 1])  : 0.f;
    float dy = (i > 0)  ? (yyv - yy[idx - WW]) : 0.f;
    g_t[idx] = g_x[idx] - TAUF * (dx + dy);

    // gradient of xbar (end-padded with zeros)
    float xb = g_xbar[idx];
    float gx = (j < WW - 1) ? (xb - g_xbar[idx + 1])  : 0.f;
    float gy = (i < HH - 1) ? (xb - g_xbar[idx + WW]) : 0.f;

    float nyx = yxv + TAUF * gx;
    float nyy = yyv + TAUF * gy;
    float denom = fmaxf(fabsf(nyx), fabsf(nyy)) + EPSF;
    float inv = 1.f / denom;
    oyx[idx] = nyx * inv;
    oyy[idx] = nyy * inv;
}

// ---------------- phase 1: rpart[kc][i][b] = sum_{j in chunk} A[i][j] * t[b][j] ----------
// grid: (128 row-blocks of 32, 2 K-chunks of 8192), 256 threads
__global__ __launch_bounds__(256, 2) void k_gemv1() {
    __shared__ float ts[8][1024];
    int tid = threadIdx.x;
    int lane = tid & 31;
    int g = tid >> 5;                    // 8 row-groups of 4 rows
    int r0 = blockIdx.x * 32;
    int k0 = blockIdx.y * 8192;

    const __half* ap[4];
#pragma unroll
    for (int rr = 0; rr < 4; rr++)
        ap[rr] = g_Ah + (size_t)(r0 + g * 4 + rr) * NN + k0;

    ull acc[4][8];
#pragma unroll
    for (int rr = 0; rr < 4; rr++)
#pragma unroll
        for (int b = 0; b < 8; b++) acc[rr][b] = 0ull;

    for (int tt = 0; tt < 8; tt++) {
        __syncthreads();
        int kt = k0 + tt * 1024;
#pragma unroll
        for (int b = 0; b < 8; b++)
            *reinterpret_cast<float4*>(&ts[b][tid * 4]) =
                *reinterpret_cast<const float4*>(&g_t[b * NN + kt + tid * 4]);
        __syncthreads();

#pragma unroll 2
        for (int s = 0; s < 16; s++) {
            int lc = s * 64 + lane * 2;          // local column (pair) in tile
            ull a2[4];
#pragma unroll
            for (int rr = 0; rr < 4; rr++) {
                __half2 h = *reinterpret_cast<const __half2*>(ap[rr] + tt * 1024 + lc);
                a2[rr] = h2_to_f32x2(h);
            }
#pragma unroll
            for (int b = 0; b < 8; b++) {
                ull tv = *reinterpret_cast<const ull*>(&ts[b][lc]);
#pragma unroll
                for (int rr = 0; rr < 4; rr++)
                    acc[rr][b] = fma2(a2[rr], tv, acc[rr][b]);
            }
        }
    }

    // reduce across lanes (each lane covered distinct columns)
#pragma unroll
    for (int rr = 0; rr < 4; rr++) {
#pragma unroll
        for (int b = 0; b < 8; b++) {
            float2 f = unpack2(acc[rr][b]);
            float v = f.x + f.y;
            v += __shfl_xor_sync(0xffffffffu, v, 16);
            v += __shfl_xor_sync(0xffffffffu, v, 8);
            v += __shfl_xor_sync(0xffffffffu, v, 4);
            v += __shfl_xor_sync(0xffffffffu, v, 2);
            v += __shfl_xor_sync(0xffffffffu, v, 1);
            if (lane == 0)
                g_rpart[blockIdx.y][r0 + g * 4 + rr][b] = v;
        }
    }
}

// ---------------- phase 2: gpart[blk][b][j] = sum_{i in block} r[b][i]*A[i][j] ----------
// grid: (16 column-slices of 1024, 16 row-blocks of 256), 256 threads
__global__ __launch_bounds__(256, 2) void k_gemv2(const float* __restrict__ meas) {
    __shared__ ull r2s[256 * 8];        // duplicated (r,r) per (row,batch), 16 KB
    int tid = threadIdx.x;
    int c0 = blockIdx.x * 1024;
    int i0 = blockIdx.y * 256;

#pragma unroll
    for (int k = 0; k < 8; k++) {
        int e = tid + k * 256;          // e = il*8 + b
        int il = e >> 3, b = e & 7;
        int i = i0 + il;
        float v = g_rpart[0][i][b] + g_rpart[1][i][b] - meas[b * MM + i];
        r2s[e] = pack2(v, v);
    }
    __syncthreads();

    int c = c0 + tid * 4;               // 4 consecutive columns per thread
    ull acc[2][8];
#pragma unroll
    for (int q = 0; q < 2; q++)
#pragma unroll
        for (int b = 0; b < 8; b++) acc[q][b] = 0ull;

#pragma unroll 4
    for (int i = 0; i < 256; i++) {
        const uint2 u = *reinterpret_cast<const uint2*>(g_Ah + (size_t)(i0 + i) * NN + c);
        __half2 h0 = *reinterpret_cast<const __half2*>(&u.x);
        __half2 h1 = *reinterpret_cast<const __half2*>(&u.y);
        ull a01 = h2_to_f32x2(h0);
        ull a23 = h2_to_f32x2(h1);
        const ull* rrow = &r2s[i * 8];
#pragma unroll
        for (int b = 0; b < 8; b++) {
            ull rv = rrow[b];           // broadcast LDS
            acc[0][b] = fma2(a01, rv, acc[0][b]);
            acc[1][b] = fma2(a23, rv, acc[1][b]);
        }
    }

#pragma unroll
    for (int b = 0; b < 8; b++) {
        float2 f0 = unpack2(acc[0][b]);
        float2 f1 = unpack2(acc[1][b]);
        float4 o = make_float4(f0.x, f0.y, f1.x, f1.y);
        *reinterpret_cast<float4*>(&g_gpart[((size_t)(blockIdx.y * 8 + b)) * NN + c]) = o;
    }
}

// ---------------- finish: x = t - grad ; xbar = 2x - xbar_old ----------------
__global__ void k_fin() {
    int idx = blockIdx.x * blockDim.x + threadIdx.x;
    if (idx >= BN) return;
    int b = idx >> 14;                  // NN = 2^14
    int j = idx & (NN - 1);
    float s = 0.f;
#pragma unroll
    for (int blk = 0; blk < 16; blk++)
        s += g_gpart[((size_t)(blk * 8 + b)) * NN + j];
    float xn = g_t[idx] - s;
    float xbo = g_xbar[idx];
    g_x[idx] = xn;
    g_xbar[idx] = 2.f * xn - xbo;
}

// ---------------- output copy ----------------
__global__ void k_copy(float* __restrict__ out) {
    int idx = blockIdx.x * blockDim.x + threadIdx.x;
    if (idx < BN) out[idx] = g_x[idx];
}

// ---------------- launch ----------------
extern "C" void kernel_launch(void* const* d_in, const int* in_sizes, int n_in,
                              void* d_out, int out_size) {
    const float* meas = (const float*)d_in[0];
    const float* A    = (const float*)d_in[1];
    if (n_in >= 2 && in_sizes[0] != BB * MM) {   // defensive: identify by size
        meas = (const float*)d_in[1];
        A    = (const float*)d_in[0];
    }
    float* out = (float*)d_out;

    k_convert<<<(int)(((size_t)MM * NN) / 8 / 256), 256>>>(A);
    k_zero<<<BN / 256, 256>>>();

    for (int it = 0; it < ITERS; it++) {
        int bi = it & 1;
        k_tv<<<BN / 256, 256>>>(bi);
        k_gemv1<<<dim3(MM / 32, 2), 256>>>();
        k_gemv2<<<dim3(NN / 1024, MM / 256), 256>>>(meas);
        k_fin<<<BN / 256, 256>>>();
    }
    k_copy<<<BN / 256, 256>>>(out);
}

// round 3
// speedup vs baseline: 1.2739x; 1.2739x over previous
#include <cuda_runtime.h>
#include <cuda_fp16.h>

typedef unsigned long long ull;

#define BB   8
#define MM   4096
#define NN   16384
#define HH   128
#define WW   128
#define BN   (BB*NN)
#define TAUF 0.01f
#define EPSF 1e-8f
#define ITERS 100

#define KC1   4          // gemv1 K-chunks (4096 cols each)
#define RB2   32         // gemv2 row-blocks (128 rows each)

// ---------------- device state (no allocations allowed) ----------------
__device__ __half g_Ah[(size_t)MM * NN];          // A in fp16, 128 MB
__device__ float  g_x[BN];
__device__ float  g_xbar[BN];
__device__ float  g_t[BN];
__device__ float  g_yb[2][2][BN];                 // ping-pong y
__device__ float  g_rpart[KC1][MM][BB];           // phase-1 K-split partials
__device__ float  g_gpart[(size_t)RB2 * BB * NN]; // phase-2 M-split partials (16 MB)

// ---------------- packed f32x2 helpers ----------------
__device__ __forceinline__ ull pack2(float x, float y) {
    ull r;
    asm("mov.b64 %0, {%1, %2};" : "=l"(r) : "f"(x), "f"(y));
    return r;
}
__device__ __forceinline__ float2 unpack2(ull v) {
    float x, y;
    asm("mov.b64 {%0, %1}, %2;" : "=f"(x), "=f"(y) : "l"(v));
    return make_float2(x, y);
}
__device__ __forceinline__ ull fma2(ull a, ull b, ull c) {
    ull d;
    asm("fma.rn.f32x2 %0, %1, %2, %3;" : "=l"(d) : "l"(a), "l"(b), "l"(c));
    return d;
}
__device__ __forceinline__ ull h2u_to_f32x2(unsigned u) {
    __half2 h = *reinterpret_cast<__half2*>(&u);
    float2 f = __half22float2(h);
    return pack2(f.x, f.y);
}

// ---------------- A fp32 -> fp16 conversion ----------------
__global__ void k_convert(const float* __restrict__ A) {
    size_t gid = (size_t)blockIdx.x * blockDim.x + threadIdx.x;   // each handles 8
    size_t base = gid * 8;
    float4 a = *reinterpret_cast<const float4*>(A + base);
    float4 b = *reinterpret_cast<const float4*>(A + base + 4);
    __half2 h0 = __floats2half2_rn(a.x, a.y);
    __half2 h1 = __floats2half2_rn(a.z, a.w);
    __half2 h2 = __floats2half2_rn(b.x, b.y);
    __half2 h3 = __floats2half2_rn(b.z, b.w);
    uint4 o;
    o.x = *reinterpret_cast<unsigned*>(&h0);
    o.y = *reinterpret_cast<unsigned*>(&h1);
    o.z = *reinterpret_cast<unsigned*>(&h2);
    o.w = *reinterpret_cast<unsigned*>(&h3);
    reinterpret_cast<uint4*>(g_Ah)[gid] = o;
}

// ---------------- zero init ----------------
__global__ void k_zero() {
    int idx = blockIdx.x * blockDim.x + threadIdx.x;
    if (idx < BN) {
        g_x[idx] = 0.f; g_xbar[idx] = 0.f;
        g_yb[0][0][idx] = 0.f; g_yb[0][1][idx] = 0.f;
    }
}

// ---------------- TV stencil ----------------
__global__ void k_tv(int bi) {
    int idx = blockIdx.x * blockDim.x + threadIdx.x;
    if (idx >= BN) return;
    int p = idx & (NN - 1);
    int i = p >> 7;
    int j = p & 127;

    const float* yx = g_yb[bi][0];
    const float* yy = g_yb[bi][1];
    float*       oyx = g_yb[bi ^ 1][0];
    float*       oyy = g_yb[bi ^ 1][1];

    float yxv = yx[idx];
    float yyv = yy[idx];

    float dx = (j > 0)  ? (yxv - yx[idx - 1])  : 0.f;
    float dy = (i > 0)  ? (yyv - yy[idx - WW]) : 0.f;
    g_t[idx] = g_x[idx] - TAUF * (dx + dy);

    float xb = g_xbar[idx];
    float gx = (j < WW - 1) ? (xb - g_xbar[idx + 1])  : 0.f;
    float gy = (i < HH - 1) ? (xb - g_xbar[idx + WW]) : 0.f;

    float nyx = yxv + TAUF * gx;
    float nyy = yyv + TAUF * gy;
    float denom = fmaxf(fabsf(nyx), fabsf(nyy)) + EPSF;
    float inv = 1.f / denom;
    oyx[idx] = nyx * inv;
    oyy[idx] = nyy * inv;
}

// ---------------- phase 1: rpart[kc][i][b] = sum_{j in chunk} A[i][j]*t[b][j] ----
// grid (MM/32, KC1); 256 threads; warp = 4 rows; lane owns 8 consecutive cols.
// t tile staged in smem as swizzled f32x2 pairs (conflict-free LDS.64).
__global__ __launch_bounds__(256, 2) void k_gemv1() {
    __shared__ ull ts[8 * 512];          // 8 batches x 512 pairs = 32 KB
    int tid = threadIdx.x;
    int lane = tid & 31;
    int g = tid >> 5;
    int r0 = blockIdx.x * 32 + g * 4;
    int k0 = blockIdx.y * 4096;

    const __half* ap = g_Ah + (size_t)r0 * NN + k0;

    ull acc[4][8];
#pragma unroll
    for (int rr = 0; rr < 4; rr++)
#pragma unroll
        for (int b = 0; b < 8; b++) acc[rr][b] = 0ull;

    int Xsw = (lane >> 2) & 3;           // pair swizzle for this lane

    for (int tt = 0; tt < 4; tt++) {     // 4 tiles of 1024 cols
        __syncthreads();
        int kt = k0 + tt * 1024;
        int P0 = tid * 2;
        int P0s = P0 ^ ((P0 >> 4) & 3);
        int P1 = P0 + 1;
        int P1s = P1 ^ ((P1 >> 4) & 3);
#pragma unroll
        for (int b = 0; b < 8; b++) {
            float4 v = *reinterpret_cast<const float4*>(&g_t[b * NN + kt + tid * 4]);
            ts[b * 512 + P0s] = pack2(v.x, v.y);
            ts[b * 512 + P1s] = pack2(v.z, v.w);
        }
        __syncthreads();

#pragma unroll 2
        for (int s = 0; s < 4; s++) {
            int col = tt * 1024 + s * 256 + lane * 8;
            uint4 a[4];
#pragma unroll
            for (int rr = 0; rr < 4; rr++)
                a[rr] = *reinterpret_cast<const uint4*>(ap + (size_t)rr * NN + col);

            int Pb = s * 128 + lane * 4;
#pragma unroll
            for (int p = 0; p < 4; p++) {
                int Ps = (Pb + p) ^ Xsw;
                ull a2[4];
                unsigned ua0 = (p == 0) ? a[0].x : (p == 1) ? a[0].y : (p == 2) ? a[0].z : a[0].w;
                unsigned ua1 = (p == 0) ? a[1].x : (p == 1) ? a[1].y : (p == 2) ? a[1].z : a[1].w;
                unsigned ua2 = (p == 0) ? a[2].x : (p == 1) ? a[2].y : (p == 2) ? a[2].z : a[2].w;
                unsigned ua3 = (p == 0) ? a[3].x : (p == 1) ? a[3].y : (p == 2) ? a[3].z : a[3].w;
                a2[0] = h2u_to_f32x2(ua0);
                a2[1] = h2u_to_f32x2(ua1);
                a2[2] = h2u_to_f32x2(ua2);
                a2[3] = h2u_to_f32x2(ua3);
#pragma unroll
                for (int b = 0; b < 8; b++) {
                    ull tv = ts[b * 512 + Ps];
#pragma unroll
                    for (int rr = 0; rr < 4; rr++)
                        acc[rr][b] = fma2(a2[rr], tv, acc[rr][b]);
                }
            }
        }
    }

#pragma unroll
    for (int rr = 0; rr < 4; rr++) {
#pragma unroll
        for (int b = 0; b < 8; b++) {
            float2 f = unpack2(acc[rr][b]);
            float v = f.x + f.y;
            v += __shfl_xor_sync(0xffffffffu, v, 16);
            v += __shfl_xor_sync(0xffffffffu, v, 8);
            v += __shfl_xor_sync(0xffffffffu, v, 4);
            v += __shfl_xor_sync(0xffffffffu, v, 2);
            v += __shfl_xor_sync(0xffffffffu, v, 1);
            if (lane == 0)
                g_rpart[blockIdx.y][r0 + rr][b] = v;
        }
    }
}

// ---------------- phase 2: gpart[blk][b][j] = sum_{i in block} r[b][i]*A[i][j] ----
// grid (NN/2048, RB2); 256 threads; thread owns 8 consecutive cols (uint4 A loads).
__global__ __launch_bounds__(256, 2) void k_gemv2(const float* __restrict__ meas) {
    __shared__ ull r2s[128 * 8];         // (row, batch) -> (r,r) packed, 8 KB
    int tid = threadIdx.x;
    int c0 = blockIdx.x * 2048;
    int i0 = blockIdx.y * 128;

#pragma unroll
    for (int k = 0; k < 4; k++) {
        int e = tid + k * 256;           // e = il*8 + b, 1024 entries
        int il = e >> 3, b = e & 7;
        int i = i0 + il;
        float v = g_rpart[0][i][b] + g_rpart[1][i][b]
                + g_rpart[2][i][b] + g_rpart[3][i][b] - meas[b * MM + i];
        r2s[e] = pack2(v, v);
    }
    __syncthreads();

    int c = c0 + tid * 8;
    ull acc[4][8];
#pragma unroll
    for (int q = 0; q < 4; q++)
#pragma unroll
        for (int b = 0; b < 8; b++) acc[q][b] = 0ull;

#pragma unroll 4
    for (int i = 0; i < 128; i++) {
        uint4 u = *reinterpret_cast<const uint4*>(g_Ah + (size_t)(i0 + i) * NN + c);
        ull a0 = h2u_to_f32x2(u.x);
        ull a1 = h2u_to_f32x2(u.y);
        ull a2 = h2u_to_f32x2(u.z);
        ull a3 = h2u_to_f32x2(u.w);
        const ull* rrow = &r2s[i * 8];
#pragma unroll
        for (int b = 0; b < 8; b++) {
            ull rv = rrow[b];            // broadcast LDS
            acc[0][b] = fma2(a0, rv, acc[0][b]);
            acc[1][b] = fma2(a1, rv, acc[1][b]);
            acc[2][b] = fma2(a2, rv, acc[2][b]);
            acc[3][b] = fma2(a3, rv, acc[3][b]);
        }
    }

#pragma unroll
    for (int b = 0; b < 8; b++) {
        float2 f0 = unpack2(acc[0][b]);
        float2 f1 = unpack2(acc[1][b]);
        float2 f2 = unpack2(acc[2][b]);
        float2 f3 = unpack2(acc[3][b]);
        float* dst = &g_gpart[((size_t)(blockIdx.y * 8 + b)) * NN + c];
        *reinterpret_cast<float4*>(dst)     = make_float4(f0.x, f0.y, f1.x, f1.y);
        *reinterpret_cast<float4*>(dst + 4) = make_float4(f2.x, f2.y, f3.x, f3.y);
    }
}

// ---------------- finish: x = t - grad ; xbar = 2x - xbar_old ----------------
__global__ void k_fin() {
    int idx = blockIdx.x * blockDim.x + threadIdx.x;
    if (idx >= BN) return;
    int b = idx >> 14;
    int j = idx & (NN - 1);
    float s = 0.f;
#pragma unroll
    for (int blk = 0; blk < RB2; blk++)
        s += g_gpart[((size_t)(blk * 8 + b)) * NN + j];
    float xn = g_t[idx] - s;
    float xbo = g_xbar[idx];
    g_x[idx] = xn;
    g_xbar[idx] = 2.f * xn - xbo;
}

// ---------------- output copy ----------------
__global__ void k_copy(float* __restrict__ out) {
    int idx = blockIdx.x * blockDim.x + threadIdx.x;
    if (idx < BN) out[idx] = g_x[idx];
}

// ---------------- launch ----------------
extern "C" void kernel_launch(void* const* d_in, const int* in_sizes, int n_in,
                              void* d_out, int out_size) {
    const float* meas = (const float*)d_in[0];
    const float* A    = (const float*)d_in[1];
    if (n_in >= 2 && in_sizes[0] != BB * MM) {
        meas = (const float*)d_in[1];
        A    = (const float*)d_in[0];
    }
    float* out = (float*)d_out;

    k_convert<<<(int)(((size_t)MM * NN) / 8 / 256), 256>>>(A);
    k_zero<<<BN / 256, 256>>>();

    for (int it = 0; it < ITERS; it++) {
        int bi = it & 1;
        k_tv<<<BN / 256, 256>>>(bi);
        k_gemv1<<<dim3(MM / 32, KC1), 256>>>();
        k_gemv2<<<dim3(NN / 2048, RB2), 256>>>(meas);
        k_fin<<<BN / 256, 256>>>();
    }
    k_copy<<<BN / 256, 256>>>(out);
}